// round 8
// baseline (speedup 1.0000x reference)
#include <cuda_runtime.h>
#include <cstdint>

// Problem constants: B=16, H=8, R=400, F=256, dilated 2^k = 8
#define BH    128
#define RDIM  400
#define FDIM  256
#define NROWS (BH * RDIM)   // 51200

// tf32-rounded copy of W (tiny; keeps GEMM B-operand unbiased-rounded)
__device__ float g_Wt[FDIM * FDIM];

// ---------------------------------------------------------------------------
// helpers
// ---------------------------------------------------------------------------
__device__ __forceinline__ uint32_t smem_u32(const void* p) {
    uint32_t a;
    asm("{ .reg .u64 t; cvta.to.shared.u64 t, %1; cvt.u32.u64 %0, t; }"
        : "=r"(a) : "l"(p));
    return a;
}

__device__ __forceinline__ float f2tf32(float x) {
    uint32_t r;
    asm("cvt.rna.tf32.f32 %0, %1;" : "=r"(r) : "f"(x));
    return __uint_as_float(r);
}

__device__ __forceinline__ void ldsm_x4(uint32_t r[4], uint32_t addr) {
    asm volatile("ldmatrix.sync.aligned.m8n8.x4.shared.b16 {%0,%1,%2,%3}, [%4];"
                 : "=r"(r[0]), "=r"(r[1]), "=r"(r[2]), "=r"(r[3]) : "r"(addr));
}

__device__ __forceinline__ void mma_tf32(float c[4], const uint32_t a[4],
                                         const uint32_t b0, const uint32_t b1) {
    asm volatile(
        "mma.sync.aligned.m16n8k8.row.col.f32.tf32.tf32.f32 "
        "{%0,%1,%2,%3}, {%4,%5,%6,%7}, {%8,%9}, {%0,%1,%2,%3};"
        : "+f"(c[0]), "+f"(c[1]), "+f"(c[2]), "+f"(c[3])
        : "r"(a[0]), "r"(a[1]), "r"(a[2]), "r"(a[3]), "r"(b0), "r"(b1));
}

__device__ __forceinline__ void cp_async16(uint32_t saddr, const void* gaddr) {
    asm volatile("cp.async.cg.shared.global [%0], [%1], 16;"
                 :: "r"(saddr), "l"(gaddr));
}
#define CP_COMMIT() asm volatile("cp.async.commit_group;")
#define CP_WAIT1()  asm volatile("cp.async.wait_group 1;")
#define CP_WAIT0()  asm volatile("cp.async.wait_group 0;")

// ---------------------------------------------------------------------------
// Kernel 0: W -> tf32-rounded copy (rna, unbiased)
// ---------------------------------------------------------------------------
__global__ void conv_w_kernel(const float4* __restrict__ W, float4* __restrict__ Wt)
{
    int i = blockIdx.x * 256 + threadIdx.x;     // 64 blocks x 256 = 16384 float4
    float4 w = W[i];
    w.x = f2tf32(w.x); w.y = f2tf32(w.y); w.z = f2tf32(w.z); w.w = f2tf32(w.w);
    Wt[i] = w;
}

// ---------------------------------------------------------------------------
// Fused kernel: per CTA of 64 rows:
//  Phase A: rank columns {0,8,9,10,11,12} of each A row (warp-per-row),
//           build (pos,val) lists (+diag) in smem.
//  Phase B: agg tile [64 x 256] gathered from feats directly into smem (tf32).
//  Phase C: out = relu(agg @ W^T + b) + feats via mma.sync tf32, W streamed
//           double-buffered cp.async, epilogue staged in idle B buffer.
// ---------------------------------------------------------------------------
#define MROWS 64
#define ATS   260                         // A-tile row stride (floats)
#define BTS   36                          // B-tile row stride (floats)
#define A_BYTES (MROWS * ATS * 4)         // 66560
#define B_OFF   A_BYTES
#define B_BUF   (128 * BTS * 4)           // 18432 per stage
#define POS_OFF (B_OFF + 2 * B_BUF)       // 103424
#define VAL_OFF (POS_OFF + MROWS * 8 * 4) // 105472
#define CNT_OFF (VAL_OFF + MROWS * 8 * 4) // 107520
#define SMEM_BYTES (CNT_OFF + MROWS * 4)  // 107776
#define EP_STRIDE 132                     // epilogue stage stride (floats)

extern __shared__ char sm_raw[];

__global__ __launch_bounds__(256, 2) void fused_gcn_kernel(
    const float* __restrict__ A,
    const float* __restrict__ feats,
    const float* __restrict__ Wt,     // tf32 bits, [N,K] row-major
    const float* __restrict__ bias,
    float* __restrict__ out)
{
    float* sA   = reinterpret_cast<float*>(sm_raw);
    int*   sPos = reinterpret_cast<int*>(sm_raw + POS_OFF);
    float* sVal = reinterpret_cast<float*>(sm_raw + VAL_OFF);
    int*   sCnt = reinterpret_cast<int*>(sm_raw + CNT_OFF);
    const uint32_t sb = smem_u32(sm_raw);

    const int t   = threadIdx.x;
    const int wid = t >> 5;
    const int lid = t & 31;
    const int m0  = blockIdx.x * MROWS;

    // Prefetch W chunk 0 of half 0 (B buffer untouched until Phase C)
    {
        const uint32_t sdst = sb + B_OFF;
        #pragma unroll
        for (int u = 0; u < 4; u++) {
            int e = u * 256 + t;            // 0..1023
            int rr = e >> 3, c4 = e & 7;
            cp_async16(sdst + ((uint32_t)(rr * BTS + c4 * 4) << 2),
                       Wt + (size_t)rr * FDIM + c4 * 4);
        }
        CP_COMMIT();
    }

    // ---------------- Phase A: ranks ----------------
    for (int r = wid; r < MROWS; r += 8) {
        const int grow = m0 + r;
        const int i    = grow % RDIM;
        const float*  arow = A + (size_t)grow * RDIM;
        const float4* a4   = reinterpret_cast<const float4*>(arow);

        const float v0 = __ldg(arow + 0);
        const float v1 = __ldg(arow + 8);
        const float v2 = __ldg(arow + 9);
        const float v3 = __ldg(arow + 10);
        const float v4 = __ldg(arow + 11);
        const float v5 = __ldg(arow + 12);

        int c0 = 0, c1 = 0, c2 = 0, c3 = 0, c4c = 0, c5 = 0;
        for (int q = lid; q < RDIM / 4; q += 32) {
            float4 f = __ldg(&a4[q]);
            int j = q * 4;
            // rank(c) = #(a_j > a_c) + #(j<c && a_j == a_c)
            c0  += (f.x > v0) + (f.y > v0) + (f.z > v0) + (f.w > v0);
            c1  += ((f.x > v1) | ((f.x == v1) & (j     < 8)))
                 + ((f.y > v1) | ((f.y == v1) & (j + 1 < 8)))
                 + ((f.z > v1) | ((f.z == v1) & (j + 2 < 8)))
                 + ((f.w > v1) | ((f.w == v1) & (j + 3 < 8)));
            c2  += ((f.x > v2) | ((f.x == v2) & (j     < 9)))
                 + ((f.y > v2) | ((f.y == v2) & (j + 1 < 9)))
                 + ((f.z > v2) | ((f.z == v2) & (j + 2 < 9)))
                 + ((f.w > v2) | ((f.w == v2) & (j + 3 < 9)));
            c3  += ((f.x > v3) | ((f.x == v3) & (j     < 10)))
                 + ((f.y > v3) | ((f.y == v3) & (j + 1 < 10)))
                 + ((f.z > v3) | ((f.z == v3) & (j + 2 < 10)))
                 + ((f.w > v3) | ((f.w == v3) & (j + 3 < 10)));
            c4c += ((f.x > v4) | ((f.x == v4) & (j     < 11)))
                 + ((f.y > v4) | ((f.y == v4) & (j + 1 < 11)))
                 + ((f.z > v4) | ((f.z == v4) & (j + 2 < 11)))
                 + ((f.w > v4) | ((f.w == v4) & (j + 3 < 11)));
            c5  += ((f.x > v5) | ((f.x == v5) & (j     < 12)))
                 + ((f.y > v5) | ((f.y == v5) & (j + 1 < 12)))
                 + ((f.z > v5) | ((f.z == v5) & (j + 2 < 12)))
                 + ((f.w > v5) | ((f.w == v5) & (j + 3 < 12)));
        }
        c0  = (int)__reduce_add_sync(0xffffffffu, (unsigned)c0);
        c1  = (int)__reduce_add_sync(0xffffffffu, (unsigned)c1);
        c2  = (int)__reduce_add_sync(0xffffffffu, (unsigned)c2);
        c3  = (int)__reduce_add_sync(0xffffffffu, (unsigned)c3);
        c4c = (int)__reduce_add_sync(0xffffffffu, (unsigned)c4c);
        c5  = (int)__reduce_add_sync(0xffffffffu, (unsigned)c5);

        if (lid == 0) {
            int p[6] = {c0, c1, c2, c3, c4c, c5};
            bool diag = false;
            #pragma unroll
            for (int k = 0; k < 6; k++) {
                sPos[r * 8 + k] = p[k];
                sVal[r * 8 + k] = __ldg(arow + p[k]);
                if (p[k] == i) diag = true;
            }
            int n = 6;
            if (!diag) { sPos[r * 8 + 6] = i; sVal[r * 8 + 6] = __ldg(arow + i); n = 7; }
            sCnt[r] = n;
        }
    }
    __syncthreads();

    // ---------------- Phase B: gather agg tile into smem (tf32) ----------------
    #pragma unroll 2
    for (int r = 0; r < MROWS; r++) {
        const int grow = m0 + r;
        const int bh   = grow / RDIM;
        const float* fb = feats + (size_t)bh * RDIM * FDIM;
        const int n = sCnt[r];
        float acc = 0.f;
        #pragma unroll
        for (int m = 0; m < 7; m++) {
            if (m < n)
                acc += sVal[r * 8 + m] * __ldg(&fb[(size_t)sPos[r * 8 + m] * FDIM + t]);
        }
        sA[r * ATS + t] = f2tf32(acc);
    }
    __syncthreads();

    // ---------------- Phase C: GEMM + epilogue ----------------
    const int wm = wid >> 2;        // 0..1  (32 rows each)
    const int wn = wid & 3;         // 0..3  (32 cols each)

    // ldmatrix lane base addresses (bytes)
    const uint32_t aBase = sb +
        ((uint32_t)((wm * 32 + ((lid >> 3) & 1) * 8 + (lid & 7)) * ATS
                    + (lid >> 4) * 4) << 2);
    const uint32_t bBase = sb + B_OFF +
        ((uint32_t)((wn * 32 + (lid >> 4) * 8 + (lid & 7)) * BTS
                    + ((lid >> 3) & 1) * 4) << 2);

    float* ep = reinterpret_cast<float*>(sm_raw + B_OFF + B_BUF);   // stage in buf1

    for (int h = 0; h < 2; h++) {
        const int n0h = h * 128;

        float acc[2][4][4];
        #pragma unroll
        for (int a = 0; a < 2; a++)
            #pragma unroll
            for (int j = 0; j < 4; j++)
                #pragma unroll
                for (int k = 0; k < 4; k++) acc[a][j][k] = 0.f;

        for (int c = 0; c < 8; c++) {
            // issue next chunk (or half-1 chunk-0 prefetch into buf0)
            if (c < 7 || h == 0) {
                const int nh = (c < 7) ? n0h : 128;
                const int nc = (c < 7) ? (c + 1) : 0;
                const int st = (c < 7) ? ((c + 1) & 1) : 0;
                const uint32_t sdst = sb + B_OFF + (uint32_t)st * B_BUF;
                #pragma unroll
                for (int u = 0; u < 4; u++) {
                    int e = u * 256 + t;
                    int rr = e >> 3, c4 = e & 7;
                    cp_async16(sdst + ((uint32_t)(rr * BTS + c4 * 4) << 2),
                               Wt + (size_t)(nh + rr) * FDIM + nc * 32 + c4 * 4);
                }
                CP_COMMIT();
                CP_WAIT1();
            } else {
                CP_WAIT0();
            }
            __syncthreads();

            const uint32_t bS = bBase + (uint32_t)(c & 1) * B_BUF;
            const uint32_t aK = (uint32_t)(c * 32) << 2;

            #pragma unroll
            for (int ks = 0; ks < 4; ks++) {
                uint32_t afr[2][4];
                #pragma unroll
                for (int tm = 0; tm < 2; tm++)
                    ldsm_x4(afr[tm], aBase + aK + ((uint32_t)(tm * 16 * ATS + ks * 8) << 2));

                uint32_t bfr[2][4];
                #pragma unroll
                for (int jj = 0; jj < 2; jj++)
                    ldsm_x4(bfr[jj], bS + ((uint32_t)(jj * 16 * BTS + ks * 8) << 2));

                #pragma unroll
                for (int tm = 0; tm < 2; tm++)
                    #pragma unroll
                    for (int j = 0; j < 4; j++)
                        mma_tf32(acc[tm][j], afr[tm],
                                 bfr[j >> 1][(j & 1) * 2], bfr[j >> 1][(j & 1) * 2 + 1]);
            }
            __syncthreads();
        }

        // epilogue: 2 groups of 32 rows staged in buf1 region (buf0 holds prefetch)
        #pragma unroll
        for (int g = 0; g < 2; g++) {
            if (wm == g) {
                #pragma unroll
                for (int tm = 0; tm < 2; tm++) {
                    int rloc = tm * 16 + (lid >> 2);
                    int cb   = wn * 32 + (lid & 3) * 2;
                    #pragma unroll
                    for (int j = 0; j < 4; j++) {
                        *reinterpret_cast<float2*>(&ep[rloc * EP_STRIDE + cb + j * 8]) =
                            make_float2(acc[tm][j][0], acc[tm][j][1]);
                        *reinterpret_cast<float2*>(&ep[(rloc + 8) * EP_STRIDE + cb + j * 8]) =
                            make_float2(acc[tm][j][2], acc[tm][j][3]);
                    }
                }
            }
            __syncthreads();

            const float4* f4 = reinterpret_cast<const float4*>(feats);
            const float4* b4 = reinterpret_cast<const float4*>(bias);
            float4* o4 = reinterpret_cast<float4*>(out);
            #pragma unroll
            for (int it2 = 0; it2 < 4; it2++) {
                int lin = it2 * 256 + t;
                int rr  = lin >> 5;          // 0..31
                int c4  = lin & 31;          // 0..31 float4
                float4 v  = *reinterpret_cast<const float4*>(&ep[rr * EP_STRIDE + c4 * 4]);
                float4 bb = __ldg(&b4[(n0h >> 2) + c4]);
                size_t gi = (size_t)(m0 + g * 32 + rr) * (FDIM / 4) + (n0h >> 2) + c4;
                float4 ff = __ldg(&f4[gi]);
                v.x = fmaxf(v.x + bb.x, 0.f) + ff.x;
                v.y = fmaxf(v.y + bb.y, 0.f) + ff.y;
                v.z = fmaxf(v.z + bb.z, 0.f) + ff.z;
                v.w = fmaxf(v.w + bb.w, 0.f) + ff.w;
                o4[gi] = v;
            }
            __syncthreads();
        }
    }
}

// ---------------------------------------------------------------------------
extern "C" void kernel_launch(void* const* d_in, const int* in_sizes, int n_in,
                              void* d_out, int out_size)
{
    const float* A     = (const float*)d_in[0];  // [16,8,400,400]
    const float* feats = (const float*)d_in[1];  // [16,8,400,256]
    const float* W     = (const float*)d_in[2];  // [256,256]
    const float* bias  = (const float*)d_in[3];  // [256]
    float* out = (float*)d_out;

    float* Wt;
    cudaGetSymbolAddress((void**)&Wt, g_Wt);

    static bool attr_set = false;
    if (!attr_set) {
        cudaFuncSetAttribute(fused_gcn_kernel,
                             cudaFuncAttributeMaxDynamicSharedMemorySize,
                             SMEM_BYTES);
        attr_set = true;
    }

    conv_w_kernel<<<FDIM * FDIM / 4 / 256, 256>>>(
        (const float4*)W, (float4*)Wt);

    fused_gcn_kernel<<<NROWS / MROWS, 256, SMEM_BYTES>>>(
        A, feats, Wt, bias, out);
}

// round 9
// speedup vs baseline: 1.9360x; 1.9360x over previous
#include <cuda_runtime.h>
#include <cstdint>

// Problem constants: B=16, H=8, R=400, F=256, dilated 2^k = 8
#define BH    128
#define RDIM  400
#define FDIM  256
#define NROWS (BH * RDIM)   // 51200

// Scratch: agg (tf32-rounded fp32 bits) [NROWS, FDIM] = 52.4 MB, W tf32 copy
__device__ float g_agg[(size_t)NROWS * FDIM];
__device__ float g_Wt[FDIM * FDIM];

// ---------------------------------------------------------------------------
// helpers
// ---------------------------------------------------------------------------
__device__ __forceinline__ uint32_t smem_u32(const void* p) {
    uint32_t a;
    asm("{ .reg .u64 t; cvta.to.shared.u64 t, %1; cvt.u32.u64 %0, t; }"
        : "=r"(a) : "l"(p));
    return a;
}

__device__ __forceinline__ float f2tf32(float x) {
    uint32_t r;
    asm("cvt.rna.tf32.f32 %0, %1;" : "=r"(r) : "f"(x));
    return __uint_as_float(r);
}

__device__ __forceinline__ void ldsm_x4(uint32_t r[4], uint32_t addr) {
    asm volatile("ldmatrix.sync.aligned.m8n8.x4.shared.b16 {%0,%1,%2,%3}, [%4];"
                 : "=r"(r[0]), "=r"(r[1]), "=r"(r[2]), "=r"(r[3]) : "r"(addr));
}

__device__ __forceinline__ void mma_tf32(float c[4], const uint32_t a[4],
                                         const uint32_t b0, const uint32_t b1) {
    asm volatile(
        "mma.sync.aligned.m16n8k8.row.col.f32.tf32.tf32.f32 "
        "{%0,%1,%2,%3}, {%4,%5,%6,%7}, {%8,%9}, {%0,%1,%2,%3};"
        : "+f"(c[0]), "+f"(c[1]), "+f"(c[2]), "+f"(c[3])
        : "r"(a[0]), "r"(a[1]), "r"(a[2]), "r"(a[3]), "r"(b0), "r"(b1));
}

__device__ __forceinline__ void cp_async16(uint32_t saddr, const void* gaddr) {
    asm volatile("cp.async.cg.shared.global [%0], [%1], 16;"
                 :: "r"(saddr), "l"(gaddr));
}
#define CP_COMMIT() asm volatile("cp.async.commit_group;")
#define CP_WAIT(N)  asm volatile("cp.async.wait_group %0;" :: "n"(N))

// ---------------------------------------------------------------------------
// Kernel 0: W -> tf32-rounded copy (rna, unbiased)
// ---------------------------------------------------------------------------
__global__ void conv_w_kernel(const float4* __restrict__ W, float4* __restrict__ Wt)
{
    int i = blockIdx.x * 256 + threadIdx.x;     // 64 blocks x 256 = 16384 float4
    float4 w = W[i];
    w.x = f2tf32(w.x); w.y = f2tf32(w.y); w.z = f2tf32(w.z); w.w = f2tf32(w.w);
    Wt[i] = w;
}

// ---------------------------------------------------------------------------
// Kernel 1: mask + sparse gather, warp-per-row, no smem, no block barriers.
// Kept columns of row i = rank positions (descending stable sort) of columns
// {0,8,9,10,11,12}, plus diag. agg[row,:] = sum val_m * feats[pos_m,:], tf32.
// ---------------------------------------------------------------------------
__global__ __launch_bounds__(256) void mask_agg_kernel(
    const float* __restrict__ A,
    const float* __restrict__ feats,
    float* __restrict__ agg)
{
    const int lid = threadIdx.x & 31;
    const int wid = threadIdx.x >> 5;
    const int row = blockIdx.x * 8 + wid;
    const int bh  = row / RDIM;
    const int i   = row - bh * RDIM;

    const float*  arow = A + (size_t)row * RDIM;
    const float4* a4   = reinterpret_cast<const float4*>(arow);

    const float v0 = __ldg(arow + 0);
    const float v1 = __ldg(arow + 8);
    const float v2 = __ldg(arow + 9);
    const float v3 = __ldg(arow + 10);
    const float v4 = __ldg(arow + 11);
    const float v5 = __ldg(arow + 12);

    int c0 = 0, c1 = 0, c2 = 0, c3 = 0, c4c = 0, c5 = 0;
    #pragma unroll 4
    for (int q = lid; q < RDIM / 4; q += 32) {
        float4 f = __ldg(&a4[q]);
        int j = q * 4;
        // rank(c) = #(a_j > a_c) + #(j<c && a_j == a_c)  (stable descending)
        c0  += (f.x > v0) + (f.y > v0) + (f.z > v0) + (f.w > v0);
        c1  += ((f.x > v1) | ((f.x == v1) & (j     < 8)))
             + ((f.y > v1) | ((f.y == v1) & (j + 1 < 8)))
             + ((f.z > v1) | ((f.z == v1) & (j + 2 < 8)))
             + ((f.w > v1) | ((f.w == v1) & (j + 3 < 8)));
        c2  += ((f.x > v2) | ((f.x == v2) & (j     < 9)))
             + ((f.y > v2) | ((f.y == v2) & (j + 1 < 9)))
             + ((f.z > v2) | ((f.z == v2) & (j + 2 < 9)))
             + ((f.w > v2) | ((f.w == v2) & (j + 3 < 9)));
        c3  += ((f.x > v3) | ((f.x == v3) & (j     < 10)))
             + ((f.y > v3) | ((f.y == v3) & (j + 1 < 10)))
             + ((f.z > v3) | ((f.z == v3) & (j + 2 < 10)))
             + ((f.w > v3) | ((f.w == v3) & (j + 3 < 10)));
        c4c += ((f.x > v4) | ((f.x == v4) & (j     < 11)))
             + ((f.y > v4) | ((f.y == v4) & (j + 1 < 11)))
             + ((f.z > v4) | ((f.z == v4) & (j + 2 < 11)))
             + ((f.w > v4) | ((f.w == v4) & (j + 3 < 11)));
        c5  += ((f.x > v5) | ((f.x == v5) & (j     < 12)))
             + ((f.y > v5) | ((f.y == v5) & (j + 1 < 12)))
             + ((f.z > v5) | ((f.z == v5) & (j + 2 < 12)))
             + ((f.w > v5) | ((f.w == v5) & (j + 3 < 12)));
    }
    // REDUX broadcasts the total to every lane — no lane-0 serialization.
    int p[7];
    p[0] = (int)__reduce_add_sync(0xffffffffu, (unsigned)c0);
    p[1] = (int)__reduce_add_sync(0xffffffffu, (unsigned)c1);
    p[2] = (int)__reduce_add_sync(0xffffffffu, (unsigned)c2);
    p[3] = (int)__reduce_add_sync(0xffffffffu, (unsigned)c3);
    p[4] = (int)__reduce_add_sync(0xffffffffu, (unsigned)c4c);
    p[5] = (int)__reduce_add_sync(0xffffffffu, (unsigned)c5);
    p[6] = i;

    bool diag = (p[0] == i) | (p[1] == i) | (p[2] == i)
              | (p[3] == i) | (p[4] == i) | (p[5] == i);
    const int n = diag ? 6 : 7;

    // values at kept positions (warp-uniform addresses -> L1 broadcast)
    float val[7];
    #pragma unroll
    for (int m = 0; m < 7; m++) val[m] = __ldg(arow + p[m]);

    // gather: lane owns 8 consecutive features (2 float4)
    const float4* fb = reinterpret_cast<const float4*>(
        feats + (size_t)bh * RDIM * FDIM);
    float4 acc0 = make_float4(0.f, 0.f, 0.f, 0.f);
    float4 acc1 = make_float4(0.f, 0.f, 0.f, 0.f);
    #pragma unroll
    for (int m = 0; m < 7; m++) {
        if (m < n) {
            const float w = val[m];
            const float4* src = fb + (size_t)p[m] * (FDIM / 4) + lid * 2;
            float4 f0 = __ldg(src);
            float4 f1 = __ldg(src + 1);
            acc0.x += w * f0.x; acc0.y += w * f0.y;
            acc0.z += w * f0.z; acc0.w += w * f0.w;
            acc1.x += w * f1.x; acc1.y += w * f1.y;
            acc1.z += w * f1.z; acc1.w += w * f1.w;
        }
    }
    acc0.x = f2tf32(acc0.x); acc0.y = f2tf32(acc0.y);
    acc0.z = f2tf32(acc0.z); acc0.w = f2tf32(acc0.w);
    acc1.x = f2tf32(acc1.x); acc1.y = f2tf32(acc1.y);
    acc1.z = f2tf32(acc1.z); acc1.w = f2tf32(acc1.w);

    float4* ao = reinterpret_cast<float4*>(agg + (size_t)row * FDIM) + lid * 2;
    ao[0] = acc0;
    ao[1] = acc1;
}

// ---------------------------------------------------------------------------
// Kernel 2: out = relu(agg @ W^T + b) + feats via mma.sync tf32 (m16n8k8).
// CTA tile 128x128, BK=32, 8 warps in 4(M)x2(N), warp tile 32x64.
// cp.async double-buffered; smem row stride 36 floats (conflict-free ldmatrix).
// (verbatim from the validated 172us round-6 kernel)
// ---------------------------------------------------------------------------
#define MT 128
#define NT 128
#define BK 32
#define NCHUNK (FDIM / BK)      // 8
#define RS 36                   // smem row stride (floats): 144B, 16B-aligned
#define STAGE_FLOATS (2 * MT * RS)          // A + B per stage = 9216
#define SMEM_FLOATS  (2 * STAGE_FLOATS)     // 18432 floats = 73728 B
#define EPS 132                 // epilogue row stride (floats)

extern __shared__ float sm_dyn[];

__global__ __launch_bounds__(256, 2) void gemm_tf32_kernel(
    const float* __restrict__ agg,   // tf32 bits
    const float* __restrict__ Wt,    // tf32 bits, [N,K] row-major
    const float* __restrict__ bias,
    const float* __restrict__ feats,
    float* __restrict__ out)
{
    const int t   = threadIdx.x;
    const int wid = t >> 5;
    const int lid = t & 31;
    const int m0  = blockIdx.x * MT;
    const int n0  = blockIdx.y * NT;
    const int wm  = wid & 3;        // warp M index (0..3)
    const int wn  = wid >> 2;       // warp N index (0..1)

    const uint32_t sb = smem_u32(sm_dyn);

    const uint32_t aAddrBase = sb +
        ((uint32_t)((wm * 32 + ((lid >> 3) & 1) * 8 + (lid & 7)) * RS
                    + (lid >> 4) * 4) << 2);
    const uint32_t bAddrBase = sb + (uint32_t)(MT * RS * 4) +
        ((uint32_t)((wn * 64 + (lid >> 4) * 8 + (lid & 7)) * RS
                    + ((lid >> 3) & 1) * 4) << 2);

    float acc[2][8][4];
    #pragma unroll
    for (int a = 0; a < 2; a++)
        #pragma unroll
        for (int j = 0; j < 8; j++)
            #pragma unroll
            for (int k = 0; k < 4; k++) acc[a][j][k] = 0.f;

    auto issue_chunk = [&](int c, int stage) {
        const uint32_t sbase = sb + (uint32_t)(stage * STAGE_FLOATS * 4);
        #pragma unroll
        for (int u = 0; u < 8; u++) {
            int idx = u * 256 + t;          // 0..2047
            int e   = idx & 1023;
            int r   = e >> 3;
            int c4  = e & 7;
            uint32_t sd;
            const float* gs;
            if (idx < 1024) {
                sd = sbase + (uint32_t)((r * RS + c4 * 4) << 2);
                gs = agg + (size_t)(m0 + r) * FDIM + c * BK + c4 * 4;
            } else {
                sd = sbase + (uint32_t)(MT * RS * 4) + (uint32_t)((r * RS + c4 * 4) << 2);
                gs = Wt + (size_t)(n0 + r) * FDIM + c * BK + c4 * 4;
            }
            cp_async16(sd, gs);
        }
        CP_COMMIT();
    };

    issue_chunk(0, 0);

    for (int c = 0; c < NCHUNK; c++) {
        const int stage = c & 1;
        if (c + 1 < NCHUNK) {
            issue_chunk(c + 1, (c + 1) & 1);
            CP_WAIT(1);
        } else {
            CP_WAIT(0);
        }
        __syncthreads();

        const uint32_t aS = aAddrBase + (uint32_t)(stage * STAGE_FLOATS * 4);
        const uint32_t bS = bAddrBase + (uint32_t)(stage * STAGE_FLOATS * 4);

        #pragma unroll
        for (int ks = 0; ks < 4; ks++) {
            uint32_t afr[2][4];
            #pragma unroll
            for (int tm = 0; tm < 2; tm++)
                ldsm_x4(afr[tm], aS + (uint32_t)((tm * 16 * RS + ks * 8) << 2));

            uint32_t bfr[4][4];
            #pragma unroll
            for (int jj = 0; jj < 4; jj++)
                ldsm_x4(bfr[jj], bS + (uint32_t)((jj * 16 * RS + ks * 8) << 2));

            #pragma unroll
            for (int tm = 0; tm < 2; tm++)
                #pragma unroll
                for (int j = 0; j < 8; j++)
                    mma_tf32(acc[tm][j], afr[tm], bfr[j >> 1][(j & 1) * 2],
                             bfr[j >> 1][(j & 1) * 2 + 1]);
        }
        __syncthreads();
    }

    // ---- epilogue: stage accumulators to smem, then coalesced store ----
    {
        float* ep = sm_dyn;
        #pragma unroll
        for (int tm = 0; tm < 2; tm++) {
            int rbase = wm * 32 + tm * 16 + (lid >> 2);
            int cbase = wn * 64 + (lid & 3) * 2;
            #pragma unroll
            for (int j = 0; j < 8; j++) {
                float2 lo = make_float2(acc[tm][j][0], acc[tm][j][1]);
                float2 hi = make_float2(acc[tm][j][2], acc[tm][j][3]);
                *reinterpret_cast<float2*>(&ep[rbase * EPS + cbase + j * 8])       = lo;
                *reinterpret_cast<float2*>(&ep[(rbase + 8) * EPS + cbase + j * 8]) = hi;
            }
        }
        __syncthreads();

        const float4* f4 = reinterpret_cast<const float4*>(feats);
        float4* o4 = reinterpret_cast<float4*>(out);
        const float4* b4 = reinterpret_cast<const float4*>(bias);
        #pragma unroll
        for (int it = 0; it < 16; it++) {
            int lin = it * 256 + t;
            int r   = lin >> 5;          // 0..127
            int c4  = lin & 31;          // 0..31 float4s
            float4 v = *reinterpret_cast<const float4*>(&ep[r * EPS + c4 * 4]);
            float4 bb = __ldg(&b4[(n0 >> 2) + c4]);
            size_t gi = ((size_t)(m0 + r) * FDIM + n0) / 4 + c4;
            float4 ff = __ldg(&f4[gi]);
            v.x = fmaxf(v.x + bb.x, 0.f) + ff.x;
            v.y = fmaxf(v.y + bb.y, 0.f) + ff.y;
            v.z = fmaxf(v.z + bb.z, 0.f) + ff.z;
            v.w = fmaxf(v.w + bb.w, 0.f) + ff.w;
            o4[gi] = v;
        }
    }
}

// ---------------------------------------------------------------------------
extern "C" void kernel_launch(void* const* d_in, const int* in_sizes, int n_in,
                              void* d_out, int out_size)
{
    const float* A     = (const float*)d_in[0];  // [16,8,400,400]
    const float* feats = (const float*)d_in[1];  // [16,8,400,256]
    const float* W     = (const float*)d_in[2];  // [256,256]
    const float* bias  = (const float*)d_in[3];  // [256]
    float* out = (float*)d_out;

    float* agg;  cudaGetSymbolAddress((void**)&agg, g_agg);
    float* Wt;   cudaGetSymbolAddress((void**)&Wt,  g_Wt);

    static bool attr_set = false;
    if (!attr_set) {
        cudaFuncSetAttribute(gemm_tf32_kernel,
                             cudaFuncAttributeMaxDynamicSharedMemorySize,
                             SMEM_FLOATS * 4);
        attr_set = true;
    }

    conv_w_kernel<<<FDIM * FDIM / 4 / 256, 256>>>((const float4*)W, (float4*)Wt);
    mask_agg_kernel<<<NROWS / 8, 256>>>(A, feats, agg);

    dim3 grid(NROWS / MT, FDIM / NT);   // (400, 2)
    gemm_tf32_kernel<<<grid, 256, SMEM_FLOATS * 4>>>(agg, Wt, bias, feats, out);
}

// round 11
// speedup vs baseline: 1.9400x; 1.0021x over previous
#include <cuda_runtime.h>
#include <cstdint>

// Problem constants: B=16, H=8, R=400, F=256, dilated 2^k = 8
#define BH    128
#define RDIM  400
#define FDIM  256
#define NROWS (BH * RDIM)   // 51200

// Scratch: agg (tf32-rounded fp32 bits) [NROWS, FDIM] = 52.4 MB, W tf32 copy
__device__ float g_agg[(size_t)NROWS * FDIM];
__device__ float g_Wt[FDIM * FDIM];

// ---------------------------------------------------------------------------
// helpers
// ---------------------------------------------------------------------------
__device__ __forceinline__ uint32_t smem_u32(const void* p) {
    uint32_t a;
    asm("{ .reg .u64 t; cvta.to.shared.u64 t, %1; cvt.u32.u64 %0, t; }"
        : "=r"(a) : "l"(p));
    return a;
}

__device__ __forceinline__ float f2tf32(float x) {
    uint32_t r;
    asm("cvt.rna.tf32.f32 %0, %1;" : "=r"(r) : "f"(x));
    return __uint_as_float(r);
}

__device__ __forceinline__ void ldsm_x4(uint32_t r[4], uint32_t addr) {
    asm volatile("ldmatrix.sync.aligned.m8n8.x4.shared.b16 {%0,%1,%2,%3}, [%4];"
                 : "=r"(r[0]), "=r"(r[1]), "=r"(r[2]), "=r"(r[3]) : "r"(addr));
}

__device__ __forceinline__ void mma_tf32(float c[4], const uint32_t a[4],
                                         const uint32_t b0, const uint32_t b1) {
    asm volatile(
        "mma.sync.aligned.m16n8k8.row.col.f32.tf32.tf32.f32 "
        "{%0,%1,%2,%3}, {%4,%5,%6,%7}, {%8,%9}, {%0,%1,%2,%3};"
        : "+f"(c[0]), "+f"(c[1]), "+f"(c[2]), "+f"(c[3])
        : "r"(a[0]), "r"(a[1]), "r"(a[2]), "r"(a[3]), "r"(b0), "r"(b1));
}

__device__ __forceinline__ void cp_async16(uint32_t saddr, const void* gaddr) {
    asm volatile("cp.async.cg.shared.global [%0], [%1], 16;"
                 :: "r"(saddr), "l"(gaddr));
}
#define CP_COMMIT() asm volatile("cp.async.commit_group;")
#define CP_WAIT(N)  asm volatile("cp.async.wait_group %0;" :: "n"(N))

// ---------------------------------------------------------------------------
// Kernel 1: mask + sparse gather, warp-per-row, no smem, no block barriers.
// Kept columns of row i = rank positions (descending stable sort) of columns
// {0,8,9,10,11,12}, plus diag. agg[row,:] = sum val_m * feats[pos_m,:], tf32.
// Extra 64 blocks at the tail convert W -> tf32 (rna) into g_Wt.
// ---------------------------------------------------------------------------
__global__ __launch_bounds__(256) void mask_agg_kernel(
    const float* __restrict__ A,
    const float* __restrict__ feats,
    const float* __restrict__ W,
    float* __restrict__ Wt,
    float* __restrict__ agg)
{
    if (blockIdx.x >= NROWS / 8) {
        // W -> tf32 conversion (64 blocks x 256 threads x 1 float4)
        int i = (blockIdx.x - NROWS / 8) * 256 + threadIdx.x;
        float4 w = reinterpret_cast<const float4*>(W)[i];
        w.x = f2tf32(w.x); w.y = f2tf32(w.y);
        w.z = f2tf32(w.z); w.w = f2tf32(w.w);
        reinterpret_cast<float4*>(Wt)[i] = w;
        return;
    }

    const int lid = threadIdx.x & 31;
    const int wid = threadIdx.x >> 5;
    const int row = blockIdx.x * 8 + wid;
    const int bh  = row / RDIM;
    const int i   = row - bh * RDIM;

    const float*  arow = A + (size_t)row * RDIM;
    const float4* a4   = reinterpret_cast<const float4*>(arow);

    const float v0 = __ldg(arow + 0);
    const float v1 = __ldg(arow + 8);
    const float v2 = __ldg(arow + 9);
    const float v3 = __ldg(arow + 10);
    const float v4 = __ldg(arow + 11);
    const float v5 = __ldg(arow + 12);

    int c0 = 0, c1 = 0, c2 = 0, c3 = 0, c4c = 0, c5 = 0;
    #pragma unroll 4
    for (int q = lid; q < RDIM / 4; q += 32) {
        float4 f = __ldg(&a4[q]);
        int j = q * 4;
        // rank(c) = #(a_j > a_c) + #(j<c && a_j == a_c)  (stable descending)
        c0  += (f.x > v0) + (f.y > v0) + (f.z > v0) + (f.w > v0);
        c1  += ((f.x > v1) | ((f.x == v1) & (j     < 8)))
             + ((f.y > v1) | ((f.y == v1) & (j + 1 < 8)))
             + ((f.z > v1) | ((f.z == v1) & (j + 2 < 8)))
             + ((f.w > v1) | ((f.w == v1) & (j + 3 < 8)));
        c2  += ((f.x > v2) | ((f.x == v2) & (j     < 9)))
             + ((f.y > v2) | ((f.y == v2) & (j + 1 < 9)))
             + ((f.z > v2) | ((f.z == v2) & (j + 2 < 9)))
             + ((f.w > v2) | ((f.w == v2) & (j + 3 < 9)));
        c3  += ((f.x > v3) | ((f.x == v3) & (j     < 10)))
             + ((f.y > v3) | ((f.y == v3) & (j + 1 < 10)))
             + ((f.z > v3) | ((f.z == v3) & (j + 2 < 10)))
             + ((f.w > v3) | ((f.w == v3) & (j + 3 < 10)));
        c4c += ((f.x > v4) | ((f.x == v4) & (j     < 11)))
             + ((f.y > v4) | ((f.y == v4) & (j + 1 < 11)))
             + ((f.z > v4) | ((f.z == v4) & (j + 2 < 11)))
             + ((f.w > v4) | ((f.w == v4) & (j + 3 < 11)));
        c5  += ((f.x > v5) | ((f.x == v5) & (j     < 12)))
             + ((f.y > v5) | ((f.y == v5) & (j + 1 < 12)))
             + ((f.z > v5) | ((f.z == v5) & (j + 2 < 12)))
             + ((f.w > v5) | ((f.w == v5) & (j + 3 < 12)));
    }
    // REDUX broadcasts the total to every lane — no lane-0 serialization.
    int p[7];
    p[0] = (int)__reduce_add_sync(0xffffffffu, (unsigned)c0);
    p[1] = (int)__reduce_add_sync(0xffffffffu, (unsigned)c1);
    p[2] = (int)__reduce_add_sync(0xffffffffu, (unsigned)c2);
    p[3] = (int)__reduce_add_sync(0xffffffffu, (unsigned)c3);
    p[4] = (int)__reduce_add_sync(0xffffffffu, (unsigned)c4c);
    p[5] = (int)__reduce_add_sync(0xffffffffu, (unsigned)c5);
    p[6] = i;

    bool diag = (p[0] == i) | (p[1] == i) | (p[2] == i)
              | (p[3] == i) | (p[4] == i) | (p[5] == i);
    const int n = diag ? 6 : 7;

    // values at kept positions (warp-uniform addresses -> L1 broadcast)
    float val[7];
    #pragma unroll
    for (int m = 0; m < 7; m++) val[m] = __ldg(arow + p[m]);

    // gather: lane owns 8 consecutive features (2 float4)
    const float4* fb = reinterpret_cast<const float4*>(
        feats + (size_t)bh * RDIM * FDIM);
    float4 acc0 = make_float4(0.f, 0.f, 0.f, 0.f);
    float4 acc1 = make_float4(0.f, 0.f, 0.f, 0.f);
    #pragma unroll
    for (int m = 0; m < 7; m++) {
        if (m < n) {
            const float w = val[m];
            const float4* src = fb + (size_t)p[m] * (FDIM / 4) + lid * 2;
            float4 f0 = __ldg(src);
            float4 f1 = __ldg(src + 1);
            acc0.x += w * f0.x; acc0.y += w * f0.y;
            acc0.z += w * f0.z; acc0.w += w * f0.w;
            acc1.x += w * f1.x; acc1.y += w * f1.y;
            acc1.z += w * f1.z; acc1.w += w * f1.w;
        }
    }
    acc0.x = f2tf32(acc0.x); acc0.y = f2tf32(acc0.y);
    acc0.z = f2tf32(acc0.z); acc0.w = f2tf32(acc0.w);
    acc1.x = f2tf32(acc1.x); acc1.y = f2tf32(acc1.y);
    acc1.z = f2tf32(acc1.z); acc1.w = f2tf32(acc1.w);

    float4* ao = reinterpret_cast<float4*>(agg + (size_t)row * FDIM) + lid * 2;
    ao[0] = acc0;
    ao[1] = acc1;
}

// ---------------------------------------------------------------------------
// Kernel 2: out = relu(agg @ W^T + b) + feats via mma.sync tf32 (m16n8k8).
// CTA tile 128x128, BK=32, 8 warps in 4(M)x2(N), warp tile 32x64.
// 3-stage cp.async pipeline, ONE __syncthreads per chunk.
// ---------------------------------------------------------------------------
#define MT 128
#define NT 128
#define BK 32
#define NCHUNK (FDIM / BK)      // 8
#define RS 36                   // smem row stride (floats): 144B, 16B-aligned
#define STAGE_FLOATS (2 * MT * RS)          // A + B per stage = 9216
#define NSTAGE 3
#define SMEM_FLOATS  (NSTAGE * STAGE_FLOATS)  // 27648 floats = 110592 B
#define EPS 132                 // epilogue row stride (floats)

extern __shared__ float sm_dyn[];

__global__ __launch_bounds__(256, 2) void gemm_tf32_kernel(
    const float* __restrict__ agg,   // tf32 bits
    const float* __restrict__ Wt,    // tf32 bits, [N,K] row-major
    const float* __restrict__ bias,
    const float* __restrict__ feats,
    float* __restrict__ out)
{
    const int t   = threadIdx.x;
    const int wid = t >> 5;
    const int lid = t & 31;
    const int m0  = blockIdx.x * MT;
    const int n0  = blockIdx.y * NT;
    const int wm  = wid & 3;        // warp M index (0..3)
    const int wn  = wid >> 2;       // warp N index (0..1)

    const uint32_t sb = smem_u32(sm_dyn);

    const uint32_t aAddrBase = sb +
        ((uint32_t)((wm * 32 + ((lid >> 3) & 1) * 8 + (lid & 7)) * RS
                    + (lid >> 4) * 4) << 2);
    const uint32_t bAddrBase = sb + (uint32_t)(MT * RS * 4) +
        ((uint32_t)((wn * 64 + (lid >> 4) * 8 + (lid & 7)) * RS
                    + ((lid >> 3) & 1) * 4) << 2);

    float acc[2][8][4];
    #pragma unroll
    for (int a = 0; a < 2; a++)
        #pragma unroll
        for (int j = 0; j < 8; j++)
            #pragma unroll
            for (int k = 0; k < 4; k++) acc[a][j][k] = 0.f;

    auto issue_chunk = [&](int c, int stage) {
        const uint32_t sbase = sb + (uint32_t)(stage * STAGE_FLOATS * 4);
        #pragma unroll
        for (int u = 0; u < 8; u++) {
            int idx = u * 256 + t;          // 0..2047
            int e   = idx & 1023;
            int r   = e >> 3;
            int c4  = e & 7;
            uint32_t sd;
            const float* gs;
            if (idx < 1024) {
                sd = sbase + (uint32_t)((r * RS + c4 * 4) << 2);
                gs = agg + (size_t)(m0 + r) * FDIM + c * BK + c4 * 4;
            } else {
                sd = sbase + (uint32_t)(MT * RS * 4) + (uint32_t)((r * RS + c4 * 4) << 2);
                gs = Wt + (size_t)(n0 + r) * FDIM + c * BK + c4 * 4;
            }
            cp_async16(sd, gs);
        }
        CP_COMMIT();
    };

    // prologue: prefetch chunks 0 and 1
    issue_chunk(0, 0);
    issue_chunk(1, 1);
    CP_WAIT(1);              // chunk 0 complete (chunk 1 may pend)
    __syncthreads();

    #pragma unroll 1
    for (int c = 0; c < NCHUNK; c++) {
        const int stage = c % NSTAGE;
        const uint32_t aS = aAddrBase + (uint32_t)(stage * STAGE_FLOATS * 4);
        const uint32_t bS = bAddrBase + (uint32_t)(stage * STAGE_FLOATS * 4);

        #pragma unroll
        for (int ks = 0; ks < 4; ks++) {
            uint32_t afr[2][4];
            #pragma unroll
            for (int tm = 0; tm < 2; tm++)
                ldsm_x4(afr[tm], aS + (uint32_t)((tm * 16 * RS + ks * 8) << 2));

            uint32_t bfr[4][4];
            #pragma unroll
            for (int jj = 0; jj < 4; jj++)
                ldsm_x4(bfr[jj], bS + (uint32_t)((jj * 16 * RS + ks * 8) << 2));

            #pragma unroll
            for (int tm = 0; tm < 2; tm++)
                #pragma unroll
                for (int j = 0; j < 8; j++)
                    mma_tf32(acc[tm][j], afr[tm], bfr[j >> 1][(j & 1) * 2],
                             bfr[j >> 1][(j & 1) * 2 + 1]);
        }

        // prefetch chunk c+2 into stage (c+2)%3 = (c-1)%3 — safe: every warp
        // passed the previous end-of-iter sync, so reads of that stage are done.
        if (c + 2 < NCHUNK) {
            issue_chunk(c + 2, (c + 2) % NSTAGE);
            CP_WAIT(1);          // chunk c+1 complete
            __syncthreads();
        } else if (c + 1 < NCHUNK) {
            CP_WAIT(0);          // chunk c+1 complete
            __syncthreads();
        }
    }
    __syncthreads();   // all warps done with MMA before smem reuse

    // ---- epilogue: stage accumulators to smem, then coalesced store ----
    {
        float* ep = sm_dyn;
        #pragma unroll
        for (int tm = 0; tm < 2; tm++) {
            int rbase = wm * 32 + tm * 16 + (lid >> 2);
            int cbase = wn * 64 + (lid & 3) * 2;
            #pragma unroll
            for (int j = 0; j < 8; j++) {
                float2 lo = make_float2(acc[tm][j][0], acc[tm][j][1]);
                float2 hi = make_float2(acc[tm][j][2], acc[tm][j][3]);
                *reinterpret_cast<float2*>(&ep[rbase * EPS + cbase + j * 8])       = lo;
                *reinterpret_cast<float2*>(&ep[(rbase + 8) * EPS + cbase + j * 8]) = hi;
            }
        }
        __syncthreads();

        const float4* f4 = reinterpret_cast<const float4*>(feats);
        float4* o4 = reinterpret_cast<float4*>(out);
        const float4* b4 = reinterpret_cast<const float4*>(bias);
        #pragma unroll
        for (int it = 0; it < 16; it++) {
            int lin = it * 256 + t;
            int r   = lin >> 5;          // 0..127
            int c4  = lin & 31;          // 0..31 float4s
            float4 v = *reinterpret_cast<const float4*>(&ep[r * EPS + c4 * 4]);
            float4 bb = __ldg(&b4[(n0 >> 2) + c4]);
            size_t gi = ((size_t)(m0 + r) * FDIM + n0) / 4 + c4;
            float4 ff = __ldg(&f4[gi]);
            v.x = fmaxf(v.x + bb.x, 0.f) + ff.x;
            v.y = fmaxf(v.y + bb.y, 0.f) + ff.y;
            v.z = fmaxf(v.z + bb.z, 0.f) + ff.z;
            v.w = fmaxf(v.w + bb.w, 0.f) + ff.w;
            o4[gi] = v;
        }
    }
}

// ---------------------------------------------------------------------------
extern "C" void kernel_launch(void* const* d_in, const int* in_sizes, int n_in,
                              void* d_out, int out_size)
{
    const float* A     = (const float*)d_in[0];  // [16,8,400,400]
    const float* feats = (const float*)d_in[1];  // [16,8,400,256]
    const float* W     = (const float*)d_in[2];  // [256,256]
    const float* bias  = (const float*)d_in[3];  // [256]
    float* out = (float*)d_out;

    float* agg;  cudaGetSymbolAddress((void**)&agg, g_agg);
    float* Wt;   cudaGetSymbolAddress((void**)&Wt,  g_Wt);

    static bool attr_set = false;
    if (!attr_set) {
        cudaFuncSetAttribute(gemm_tf32_kernel,
                             cudaFuncAttributeMaxDynamicSharedMemorySize,
                             SMEM_FLOATS * 4);
        attr_set = true;
    }

    // 6400 mask blocks + 64 W-conversion blocks in one launch
    mask_agg_kernel<<<NROWS / 8 + 64, 256>>>(A, feats, W, Wt, agg);

    dim3 grid(NROWS / MT, FDIM / NT);   // (400, 2)
    gemm_tf32_kernel<<<grid, 256, SMEM_FLOATS * 4>>>(agg, Wt, bias, feats, out);
}

// round 12
// speedup vs baseline: 2.0873x; 1.0759x over previous
#include <cuda_runtime.h>
#include <cstdint>

// Problem constants: B=16, H=8, R=400, F=256, dilated 2^k = 8
#define BH    128
#define RDIM  400
#define FDIM  256
#define NROWS (BH * RDIM)   // 51200

// Scratch: agg (tf32-rounded fp32 bits) [NROWS, FDIM] = 52.4 MB, W tf32 copy
__device__ float g_agg[(size_t)NROWS * FDIM];
__device__ float g_Wt[FDIM * FDIM];

// ---------------------------------------------------------------------------
// helpers
// ---------------------------------------------------------------------------
__device__ __forceinline__ uint32_t smem_u32(const void* p) {
    uint32_t a;
    asm("{ .reg .u64 t; cvta.to.shared.u64 t, %1; cvt.u32.u64 %0, t; }"
        : "=r"(a) : "l"(p));
    return a;
}

__device__ __forceinline__ float f2tf32(float x) {
    uint32_t r;
    asm("cvt.rna.tf32.f32 %0, %1;" : "=r"(r) : "f"(x));
    return __uint_as_float(r);
}

__device__ __forceinline__ void ldsm_x4(uint32_t r[4], uint32_t addr) {
    asm volatile("ldmatrix.sync.aligned.m8n8.x4.shared.b16 {%0,%1,%2,%3}, [%4];"
                 : "=r"(r[0]), "=r"(r[1]), "=r"(r[2]), "=r"(r[3]) : "r"(addr));
}

__device__ __forceinline__ void mma_tf32(float c[4], const uint32_t a[4],
                                         const uint32_t b0, const uint32_t b1) {
    asm volatile(
        "mma.sync.aligned.m16n8k8.row.col.f32.tf32.tf32.f32 "
        "{%0,%1,%2,%3}, {%4,%5,%6,%7}, {%8,%9}, {%0,%1,%2,%3};"
        : "+f"(c[0]), "+f"(c[1]), "+f"(c[2]), "+f"(c[3])
        : "r"(a[0]), "r"(a[1]), "r"(a[2]), "r"(a[3]), "r"(b0), "r"(b1));
}

__device__ __forceinline__ void cp_async16(uint32_t saddr, const void* gaddr) {
    asm volatile("cp.async.cg.shared.global [%0], [%1], 16;"
                 :: "r"(saddr), "l"(gaddr));
}
#define CP_COMMIT() asm volatile("cp.async.commit_group;")
#define CP_WAIT(N)  asm volatile("cp.async.wait_group %0;" :: "n"(N))

// ---------------------------------------------------------------------------
// Kernel 1: mask + sparse gather. TWO rows per warp (double MLP), no smem,
// no block barriers. Tie-break ALU only in the first strip iteration
// (j < 128 covers all possible tie indices j < 12; later iters j >= 128).
// Tail 64 blocks convert W -> tf32 (rna) into g_Wt.
// ---------------------------------------------------------------------------
__global__ __launch_bounds__(256) void mask_agg_kernel(
    const float* __restrict__ A,
    const float* __restrict__ feats,
    const float* __restrict__ W,
    float* __restrict__ Wt,
    float* __restrict__ agg)
{
    if (blockIdx.x >= NROWS / 16) {
        // W -> tf32 conversion (64 blocks x 256 threads x 1 float4)
        int i = (blockIdx.x - NROWS / 16) * 256 + threadIdx.x;
        float4 w = reinterpret_cast<const float4*>(W)[i];
        w.x = f2tf32(w.x); w.y = f2tf32(w.y);
        w.z = f2tf32(w.z); w.w = f2tf32(w.w);
        reinterpret_cast<float4*>(Wt)[i] = w;
        return;
    }

    const int lid  = threadIdx.x & 31;
    const int wid  = threadIdx.x >> 5;
    const int row0 = blockIdx.x * 16 + wid * 2;

    const float* ar0 = A + (size_t)row0 * RDIM;
    const float* ar1 = ar0 + RDIM;
    const float4* a40 = reinterpret_cast<const float4*>(ar0);
    const float4* a41 = reinterpret_cast<const float4*>(ar1);

    float v[2][6];
    #pragma unroll
    for (int rr = 0; rr < 2; rr++) {
        const float* ar = rr ? ar1 : ar0;
        v[rr][0] = __ldg(ar + 0);
        v[rr][1] = __ldg(ar + 8);
        v[rr][2] = __ldg(ar + 9);
        v[rr][3] = __ldg(ar + 10);
        v[rr][4] = __ldg(ar + 11);
        v[rr][5] = __ldg(ar + 12);
    }

    int cnt[2][6];
    #pragma unroll
    for (int rr = 0; rr < 2; rr++)
        #pragma unroll
        for (int k = 0; k < 6; k++) cnt[rr][k] = 0;

    // ---- iteration 0 (q = lid, j = 4*lid): full tie-break logic ----
    {
        const int j = lid * 4;
        float4 f0 = __ldg(a40 + lid);
        float4 f1 = __ldg(a41 + lid);
        #pragma unroll
        for (int rr = 0; rr < 2; rr++) {
            float4 f = rr ? f1 : f0;
            cnt[rr][0] += (f.x > v[rr][0]) + (f.y > v[rr][0])
                        + (f.z > v[rr][0]) + (f.w > v[rr][0]);
            #pragma unroll
            for (int k = 1; k < 6; k++) {
                const int thr = 7 + k;   // 8..12
                cnt[rr][k] +=
                      ((f.x > v[rr][k]) | ((f.x == v[rr][k]) & (j     < thr)))
                    + ((f.y > v[rr][k]) | ((f.y == v[rr][k]) & (j + 1 < thr)))
                    + ((f.z > v[rr][k]) | ((f.z == v[rr][k]) & (j + 2 < thr)))
                    + ((f.w > v[rr][k]) | ((f.w == v[rr][k]) & (j + 3 < thr)));
            }
        }
    }
    // ---- remaining iterations: j >= 128 > 12 -> pure greater-than counts ----
    for (int q = lid + 32; q < RDIM / 4; q += 32) {
        float4 f0 = __ldg(a40 + q);
        float4 f1 = __ldg(a41 + q);
        #pragma unroll
        for (int rr = 0; rr < 2; rr++) {
            float4 f = rr ? f1 : f0;
            #pragma unroll
            for (int k = 0; k < 6; k++)
                cnt[rr][k] += (f.x > v[rr][k]) + (f.y > v[rr][k])
                            + (f.z > v[rr][k]) + (f.w > v[rr][k]);
        }
    }

    // REDUX broadcasts totals to every lane
    int   p[2][7];
    float val[2][7];
    int   n[2];
    #pragma unroll
    for (int rr = 0; rr < 2; rr++) {
        #pragma unroll
        for (int k = 0; k < 6; k++)
            p[rr][k] = (int)__reduce_add_sync(0xffffffffu, (unsigned)cnt[rr][k]);
        const int row = row0 + rr;
        const int i   = row - (row / RDIM) * RDIM;
        p[rr][6] = i;
        bool diag = (p[rr][0] == i) | (p[rr][1] == i) | (p[rr][2] == i)
                  | (p[rr][3] == i) | (p[rr][4] == i) | (p[rr][5] == i);
        n[rr] = diag ? 6 : 7;
        const float* ar = rr ? ar1 : ar0;
        #pragma unroll
        for (int m = 0; m < 7; m++) val[rr][m] = __ldg(ar + p[rr][m]);
    }

    // gather: lane owns 8 consecutive features per row (2 float4 each)
    float4 acc[2][2];
    #pragma unroll
    for (int rr = 0; rr < 2; rr++) {
        acc[rr][0] = make_float4(0.f, 0.f, 0.f, 0.f);
        acc[rr][1] = make_float4(0.f, 0.f, 0.f, 0.f);
    }

    #pragma unroll
    for (int m = 0; m < 7; m++) {
        #pragma unroll
        for (int rr = 0; rr < 2; rr++) {
            if (m < n[rr]) {
                const int row = row0 + rr;
                const int bh  = row / RDIM;
                const float4* fb = reinterpret_cast<const float4*>(
                    feats + (size_t)bh * RDIM * FDIM);
                const float w = val[rr][m];
                const float4* src = fb + (size_t)p[rr][m] * (FDIM / 4) + lid * 2;
                float4 f0 = __ldg(src);
                float4 f1 = __ldg(src + 1);
                acc[rr][0].x += w * f0.x; acc[rr][0].y += w * f0.y;
                acc[rr][0].z += w * f0.z; acc[rr][0].w += w * f0.w;
                acc[rr][1].x += w * f1.x; acc[rr][1].y += w * f1.y;
                acc[rr][1].z += w * f1.z; acc[rr][1].w += w * f1.w;
            }
        }
    }

    #pragma unroll
    for (int rr = 0; rr < 2; rr++) {
        float4 a0 = acc[rr][0], a1 = acc[rr][1];
        a0.x = f2tf32(a0.x); a0.y = f2tf32(a0.y);
        a0.z = f2tf32(a0.z); a0.w = f2tf32(a0.w);
        a1.x = f2tf32(a1.x); a1.y = f2tf32(a1.y);
        a1.z = f2tf32(a1.z); a1.w = f2tf32(a1.w);
        float4* ao = reinterpret_cast<float4*>(
            agg + (size_t)(row0 + rr) * FDIM) + lid * 2;
        ao[0] = a0;
        ao[1] = a1;
    }
}

// ---------------------------------------------------------------------------
// Kernel 2: out = relu(agg @ W^T + b) + feats via mma.sync tf32 (m16n8k8).
// CTA tile 128x128, BK=32, 8 warps in 4(M)x2(N), warp tile 32x64.
// 3-stage cp.async pipeline, ONE __syncthreads per chunk.
// Grid is (N-tiles, M-tiles) so the 2 CTAs sharing an agg M-tile are
// bid-adjacent -> second agg read hits L2.
// ---------------------------------------------------------------------------
#define MT 128
#define NT 128
#define BK 32
#define NCHUNK (FDIM / BK)      // 8
#define RS 36                   // smem row stride (floats): 144B, 16B-aligned
#define STAGE_FLOATS (2 * MT * RS)          // A + B per stage = 9216
#define NSTAGE 3
#define SMEM_FLOATS  (NSTAGE * STAGE_FLOATS)  // 27648 floats = 110592 B
#define EPS 132                 // epilogue row stride (floats)

extern __shared__ float sm_dyn[];

__global__ __launch_bounds__(256, 2) void gemm_tf32_kernel(
    const float* __restrict__ agg,   // tf32 bits
    const float* __restrict__ Wt,    // tf32 bits, [N,K] row-major
    const float* __restrict__ bias,
    const float* __restrict__ feats,
    float* __restrict__ out)
{
    const int t   = threadIdx.x;
    const int wid = t >> 5;
    const int lid = t & 31;
    const int m0  = blockIdx.y * MT;   // swapped: y = M tile
    const int n0  = blockIdx.x * NT;   // swapped: x = N tile (fast dim)
    const int wm  = wid & 3;        // warp M index (0..3)
    const int wn  = wid >> 2;       // warp N index (0..1)

    const uint32_t sb = smem_u32(sm_dyn);

    const uint32_t aAddrBase = sb +
        ((uint32_t)((wm * 32 + ((lid >> 3) & 1) * 8 + (lid & 7)) * RS
                    + (lid >> 4) * 4) << 2);
    const uint32_t bAddrBase = sb + (uint32_t)(MT * RS * 4) +
        ((uint32_t)((wn * 64 + (lid >> 4) * 8 + (lid & 7)) * RS
                    + ((lid >> 3) & 1) * 4) << 2);

    float acc[2][8][4];
    #pragma unroll
    for (int a = 0; a < 2; a++)
        #pragma unroll
        for (int j = 0; j < 8; j++)
            #pragma unroll
            for (int k = 0; k < 4; k++) acc[a][j][k] = 0.f;

    auto issue_chunk = [&](int c, int stage) {
        const uint32_t sbase = sb + (uint32_t)(stage * STAGE_FLOATS * 4);
        #pragma unroll
        for (int u = 0; u < 8; u++) {
            int idx = u * 256 + t;          // 0..2047
            int e   = idx & 1023;
            int r   = e >> 3;
            int c4  = e & 7;
            uint32_t sd;
            const float* gs;
            if (idx < 1024) {
                sd = sbase + (uint32_t)((r * RS + c4 * 4) << 2);
                gs = agg + (size_t)(m0 + r) * FDIM + c * BK + c4 * 4;
            } else {
                sd = sbase + (uint32_t)(MT * RS * 4) + (uint32_t)((r * RS + c4 * 4) << 2);
                gs = Wt + (size_t)(n0 + r) * FDIM + c * BK + c4 * 4;
            }
            cp_async16(sd, gs);
        }
        CP_COMMIT();
    };

    // prologue: prefetch chunks 0 and 1
    issue_chunk(0, 0);
    issue_chunk(1, 1);
    CP_WAIT(1);              // chunk 0 complete (chunk 1 may pend)
    __syncthreads();

    #pragma unroll 1
    for (int c = 0; c < NCHUNK; c++) {
        const int stage = c % NSTAGE;
        const uint32_t aS = aAddrBase + (uint32_t)(stage * STAGE_FLOATS * 4);
        const uint32_t bS = bAddrBase + (uint32_t)(stage * STAGE_FLOATS * 4);

        #pragma unroll
        for (int ks = 0; ks < 4; ks++) {
            uint32_t afr[2][4];
            #pragma unroll
            for (int tm = 0; tm < 2; tm++)
                ldsm_x4(afr[tm], aS + (uint32_t)((tm * 16 * RS + ks * 8) << 2));

            uint32_t bfr[4][4];
            #pragma unroll
            for (int jj = 0; jj < 4; jj++)
                ldsm_x4(bfr[jj], bS + (uint32_t)((jj * 16 * RS + ks * 8) << 2));

            #pragma unroll
            for (int tm = 0; tm < 2; tm++)
                #pragma unroll
                for (int j = 0; j < 8; j++)
                    mma_tf32(acc[tm][j], afr[tm], bfr[j >> 1][(j & 1) * 2],
                             bfr[j >> 1][(j & 1) * 2 + 1]);
        }

        // prefetch chunk c+2 into stage (c+2)%3 = (c-1)%3 — safe: every warp
        // passed the previous end-of-iter sync, so reads of that stage are done.
        if (c + 2 < NCHUNK) {
            issue_chunk(c + 2, (c + 2) % NSTAGE);
            CP_WAIT(1);          // chunk c+1 complete
            __syncthreads();
        } else if (c + 1 < NCHUNK) {
            CP_WAIT(0);          // chunk c+1 complete
            __syncthreads();
        }
    }
    __syncthreads();   // all warps done with MMA before smem reuse

    // ---- epilogue: stage accumulators to smem, then coalesced store ----
    {
        float* ep = sm_dyn;
        #pragma unroll
        for (int tm = 0; tm < 2; tm++) {
            int rbase = wm * 32 + tm * 16 + (lid >> 2);
            int cbase = wn * 64 + (lid & 3) * 2;
            #pragma unroll
            for (int j = 0; j < 8; j++) {
                float2 lo = make_float2(acc[tm][j][0], acc[tm][j][1]);
                float2 hi = make_float2(acc[tm][j][2], acc[tm][j][3]);
                *reinterpret_cast<float2*>(&ep[rbase * EPS + cbase + j * 8])       = lo;
                *reinterpret_cast<float2*>(&ep[(rbase + 8) * EPS + cbase + j * 8]) = hi;
            }
        }
        __syncthreads();

        const float4* f4 = reinterpret_cast<const float4*>(feats);
        float4* o4 = reinterpret_cast<float4*>(out);
        const float4* b4 = reinterpret_cast<const float4*>(bias);
        #pragma unroll
        for (int it = 0; it < 16; it++) {
            int lin = it * 256 + t;
            int r   = lin >> 5;          // 0..127
            int c4  = lin & 31;          // 0..31 float4s
            float4 v = *reinterpret_cast<const float4*>(&ep[r * EPS + c4 * 4]);
            float4 bb = __ldg(&b4[(n0 >> 2) + c4]);
            size_t gi = ((size_t)(m0 + r) * FDIM + n0) / 4 + c4;
            float4 ff = __ldg(&f4[gi]);
            v.x = fmaxf(v.x + bb.x, 0.f) + ff.x;
            v.y = fmaxf(v.y + bb.y, 0.f) + ff.y;
            v.z = fmaxf(v.z + bb.z, 0.f) + ff.z;
            v.w = fmaxf(v.w + bb.w, 0.f) + ff.w;
            o4[gi] = v;
        }
    }
}

// ---------------------------------------------------------------------------
extern "C" void kernel_launch(void* const* d_in, const int* in_sizes, int n_in,
                              void* d_out, int out_size)
{
    const float* A     = (const float*)d_in[0];  // [16,8,400,400]
    const float* feats = (const float*)d_in[1];  // [16,8,400,256]
    const float* W     = (const float*)d_in[2];  // [256,256]
    const float* bias  = (const float*)d_in[3];  // [256]
    float* out = (float*)d_out;

    float* agg;  cudaGetSymbolAddress((void**)&agg, g_agg);
    float* Wt;   cudaGetSymbolAddress((void**)&Wt,  g_Wt);

    static bool attr_set = false;
    if (!attr_set) {
        cudaFuncSetAttribute(gemm_tf32_kernel,
                             cudaFuncAttributeMaxDynamicSharedMemorySize,
                             SMEM_FLOATS * 4);
        attr_set = true;
    }

    // 3200 mask blocks (16 rows each) + 64 W-conversion blocks
    mask_agg_kernel<<<NROWS / 16 + 64, 256>>>(A, feats, W, Wt, agg);

    // grid: x = N tiles (fast) so agg-tile-sharing CTAs are bid-adjacent
    dim3 grid(FDIM / NT, NROWS / MT);   // (2, 400)
    gemm_tf32_kernel<<<grid, 256, SMEM_FLOATS * 4>>>(agg, Wt, bias, feats, out);
}